// round 1
// baseline (speedup 1.0000x reference)
#include <cuda_runtime.h>
#include <cstdint>

// ---------------------------------------------------------------------------
// Problem constants
// ---------------------------------------------------------------------------
#define B_       16
#define M_       100
#define NUM_CLS  80
#define HW_TOT   21824          // 128^2 + 64^2 + 32^2 + 16^2 + 8^2
#define NPIX     (B_ * HW_TOT)  // 349184

#define CLS_N    (NPIX * 82)    // 28,633,088
#define REG_N    (NPIX * 6)     //  2,095,104
#define OFF_REG  ((long long)CLS_N)
#define OFF_IND  (OFF_REG + REG_N)            // 30,728,192
#define OFF_NB   (OFF_IND + NPIX)             // 31,077,376

// Per-level tables (level offsets within HW_TOT, fw shift, stride)
__device__ __constant__ int   c_off[5]   = {0, 16384, 20480, 21504, 21760};
__device__ __constant__ int   c_shift[5] = {7, 6, 5, 4, 3};          // fw = 1<<shift
__device__ __constant__ float c_stride[5]= {8.f, 16.f, 32.f, 64.f, 128.f};

// Scratch: per-pixel compact result (no device allocation allowed -> globals)
__device__ float g_soft[NPIX];
__device__ int   g_info[NPIX];   // -1 if not pos, else winner | (label<<16)

// ---------------------------------------------------------------------------
// Kernel 1: per-pixel argmin assignment.
// grid = (86, 16), block = 256. Each block is a single (batch, level) slab.
// ---------------------------------------------------------------------------
__global__ __launch_bounds__(256) void assign_kernel(const float* __restrict__ gt)
{
    __shared__ float4 sbnd[M_];   // shrunk bounds in level coords: px1,py1,px2,py2
    __shared__ float  sarea[M_];
    __shared__ float4 sbox[M_];   // original image-space box
    __shared__ int    slbl[M_];

    const int b  = blockIdx.y;
    const int p0 = blockIdx.x * 256;
    const int t  = threadIdx.x;

    int lev;
    if      (p0 < 16384) lev = 0;
    else if (p0 < 20480) lev = 1;
    else if (p0 < 21504) lev = 2;
    else if (p0 < 21760) lev = 3;
    else                 lev = 4;

    const int   sh  = c_shift[lev];
    const int   fw  = 1 << sh;
    const float fS  = c_stride[lev];
    const float inv = 1.0f / fS;            // exact (power of two)

    if (t < M_) {
        const float* bp = gt + (b * M_ + t) * 5;
        float x1 = bp[0], y1 = bp[1], x2 = bp[2], y2 = bp[3];
        float b0 = x1 * inv, b1 = y1 * inv, b2 = x2 * inv, b3 = y2 * inv;
        float cx = (b0 + b2) * 0.5f;
        float cy = (b1 + b3) * 0.5f;
        float hw = (b2 - b0) * 0.5f * 0.2f;
        float hh = (b3 - b1) * 0.5f * 0.2f;
        float px1 = fmaxf(floorf(cx - hw), 0.0f);
        float py1 = fmaxf(floorf(cy - hh), 0.0f);
        float px2 = fminf(ceilf(cx + hw), (float)fw);
        float py2 = fminf(ceilf(cy + hh), (float)fw);
        sbnd[t]  = make_float4(px1, py1, px2, py2);
        sarea[t] = (x2 - x1) * (y2 - y1);
        sbox[t]  = make_float4(x1, y1, x2, y2);
        slbl[t]  = (int)bp[4];
    }
    __syncthreads();

    const int p = p0 + t;
    if (p >= HW_TOT) return;

    const int   local = p - c_off[lev];
    const int   y     = local >> sh;
    const int   x     = local & (fw - 1);
    const float fx    = (float)x;
    const float fy    = (float)y;

    float bestA = 1e7f;     // BIG
    int   bestJ = -1;
#pragma unroll 4
    for (int j = 0; j < M_; j++) {
        float4 bb = sbnd[j];
        bool inside = (fx >= bb.x) & (fx < bb.z) & (fy >= bb.y) & (fy < bb.w);
        float a = sarea[j];
        if (inside && (a < bestA)) { bestA = a; bestJ = j; }
    }

    float soft = 1.0f;
    int   info = -1;
    if (bestJ >= 0) {
        float4 wb = sbox[bestJ];
        float sx = (fx + 0.5f) * fS;
        float sy = (fy + 0.5f) * fS;
        float l  = sx - wb.x;
        float tt = sy - wb.y;
        float r  = wb.z - sx;
        float bt = wb.w - sy;
        const float eps = 1e-6f;
        float q1 = fminf(fmaxf(fminf(l, r)  / fmaxf(fmaxf(l, r),  eps), 0.f), 1.f);
        float q2 = fminf(fmaxf(fminf(tt, bt)/ fmaxf(fmaxf(tt, bt), eps), 0.f), 1.f);
        soft = sqrtf(q1 * q2);
        info = bestJ | (slbl[bestJ] << 16);
    }

    const int gp = b * HW_TOT + p;
    g_soft[gp] = soft;
    g_info[gp] = info;
}

// ---------------------------------------------------------------------------
// Kernel 2: cls_t writer. One thread per 4 output floats, float4 stores.
// cls element (g, c): c<80 -> (c==label && pos), c==80 -> soft, c==81 -> posf
// ---------------------------------------------------------------------------
__global__ __launch_bounds__(256) void cls_kernel(float* __restrict__ out)
{
    const int i4 = blockIdx.x * 256 + threadIdx.x;   // < CLS_N/4 == 7,158,272
    if (i4 >= CLS_N / 4) return;

    int e = i4 * 4;
    int g = e / 82;
    int c = e - g * 82;
    int   info = g_info[g];
    float soft = g_soft[g];

    float v[4];
#pragma unroll
    for (int k = 0; k < 4; k++) {
        if (c == 82) { c = 0; g++; info = g_info[g]; soft = g_soft[g]; }
        float val;
        if (info < 0) {
            val = (c == 80) ? 1.0f : 0.0f;
        } else {
            int lbl = info >> 16;
            val = (c == lbl) ? 1.0f
                : (c == 80) ? soft
                : (c == 81) ? 1.0f
                : 0.0f;
        }
        v[k] = val;
        c++;
    }
    reinterpret_cast<float4*>(out)[i4] = make_float4(v[0], v[1], v[2], v[3]);
}

// ---------------------------------------------------------------------------
// Kernel 3: reg_t (float2 per thread) + ind_t + num_boxes.
// reg element pairs per pixel: (l,t) (r,b) (soft,posf), all /(4*stride)*posf.
// ---------------------------------------------------------------------------
__global__ __launch_bounds__(256) void rest_kernel(const float* __restrict__ gt,
                                                   float* __restrict__ out)
{
    const int idx = blockIdx.x * 256 + threadIdx.x;

    if (idx < REG_N / 2) {                       // 1,047,552
        int g  = idx / 3;
        int pr = idx - g * 3;
        int   info = g_info[g];
        float soft = g_soft[g];
        float2 v;
        if (pr == 2) {
            v.x = soft;
            v.y = (info >= 0) ? 1.0f : 0.0f;
        } else if (info < 0) {
            v.x = 0.0f; v.y = 0.0f;
        } else {
            int w = info & 0xFFFF;
            int b = g / HW_TOT;
            int p = g - b * HW_TOT;
            int lev = (p < 16384) ? 0 : (p < 20480) ? 1 : (p < 21504) ? 2
                    : (p < 21760) ? 3 : 4;
            int   sh    = c_shift[lev];
            int   local = p - c_off[lev];
            int   y     = local >> sh;
            int   x     = local & ((1 << sh) - 1);
            float fS    = c_stride[lev];
            float sx    = ((float)x + 0.5f) * fS;
            float sy    = ((float)y + 0.5f) * fS;
            const float* bp = gt + (b * M_ + w) * 5;
            float inv4  = 1.0f / (4.0f * fS);    // exact power of two
            if (pr == 0) { v.x = (sx - bp[0]) * inv4; v.y = (sy - bp[1]) * inv4; }
            else         { v.x = (bp[2] - sx) * inv4; v.y = (bp[3] - sy) * inv4; }
        }
        reinterpret_cast<float2*>(out + OFF_REG)[idx] = v;
    }

    if (idx < NPIX) {
        int info = g_info[idx];
        out[OFF_IND + idx] = (info >= 0) ? (float)(info & 0xFFFF) : -1.0f;
    }

    if (idx < B_) {
        const float* bp = gt + idx * M_ * 5;
        int cnt = 0;
#pragma unroll 4
        for (int j = 0; j < M_; j++) {
            const float* q = bp + j * 5;
            if (fabsf(q[0]) + fabsf(q[1]) + fabsf(q[2]) + fabsf(q[3]) > 0.0f) cnt++;
        }
        out[OFF_NB + idx] = (float)cnt;
    }
}

// ---------------------------------------------------------------------------
extern "C" void kernel_launch(void* const* d_in, const int* in_sizes, int n_in,
                              void* d_out, int out_size)
{
    const float* gt  = (const float*)d_in[0];
    float*       out = (float*)d_out;

    dim3 grid1((HW_TOT + 255) / 256, B_);          // (86, 16)
    assign_kernel<<<grid1, 256>>>(gt);

    cls_kernel<<<(CLS_N / 4 + 255) / 256, 256>>>(out);            // 27,962 blocks
    rest_kernel<<<(REG_N / 2 + 255) / 256, 256>>>(gt, out);       //  4,092 blocks
}

// round 2
// speedup vs baseline: 2.0431x; 2.0431x over previous
#include <cuda_runtime.h>
#include <cstdint>

// ---------------------------------------------------------------------------
// Problem constants
// ---------------------------------------------------------------------------
#define B_       16
#define M_       100
#define NUM_CLS  80
#define HW_TOT   21824          // 128^2 + 64^2 + 32^2 + 16^2 + 8^2
#define NPIX     (B_ * HW_TOT)  // 349184

#define CLS_N    (NPIX * 82)    // 28,633,088
#define REG_N    (NPIX * 6)     //  2,095,104
#define OFF_REG  ((long long)CLS_N)
#define OFF_IND  (OFF_REG + REG_N)            // 30,728,192
#define OFF_NB   (OFF_IND + NPIX)             // 31,077,376

__device__ __constant__ int   c_off[5]   = {0, 16384, 20480, 21504, 21760};
__device__ __constant__ int   c_shift[5] = {7, 6, 5, 4, 3};          // fw = 1<<shift
__device__ __constant__ float c_stride[5]= {8.f, 16.f, 32.f, 64.f, 128.f};

// ---------------------------------------------------------------------------
// Fused assign + sparse-scatter kernel.
// grid = (86, 16), block = 256. Each block covers one (batch, level) slab of
// 256 pixels (level boundaries are 256-aligned). The cls/reg output regions
// are pre-zeroed by cudaMemsetAsync; this kernel writes only non-zero values.
// ---------------------------------------------------------------------------
__global__ __launch_bounds__(256) void fused_kernel(const float* __restrict__ gt,
                                                    float* __restrict__ out)
{
    __shared__ float4 sbox[M_];    // image-space box (indexed by original j)
    __shared__ int    slbl[M_];
    __shared__ float4 cbnd[M_];    // compacted candidate bounds (level coords)
    __shared__ float  carea[M_];
    __shared__ int    cj[M_];      // original index of candidate
    __shared__ int    s_cnt;
    __shared__ int    s_valid;

    const int b  = blockIdx.y;
    const int p0 = blockIdx.x * 256;
    const int t  = threadIdx.x;

    int lev;
    if      (p0 < 16384) lev = 0;
    else if (p0 < 20480) lev = 1;
    else if (p0 < 21504) lev = 2;
    else if (p0 < 21760) lev = 3;
    else                 lev = 4;

    const int   sh  = c_shift[lev];
    const int   fw  = 1 << sh;
    const float fS  = c_stride[lev];
    const float inv = 1.0f / fS;                 // exact (power of two)
    const int   off = c_off[lev];

    // block's row range at this level
    const int local0 = p0 - off;
    const int by0 = local0 >> sh;
    int       by1 = (local0 + 255) >> sh;
    if (by1 > fw - 1) by1 = fw - 1;

    if (t == 0) { s_cnt = 0; s_valid = 0; }
    __syncthreads();

    if (t < M_) {
        const float* bp = gt + (b * M_ + t) * 5;
        float x1 = bp[0], y1 = bp[1], x2 = bp[2], y2 = bp[3];
        sbox[t] = make_float4(x1, y1, x2, y2);
        slbl[t] = (int)bp[4];

        float b0 = x1 * inv, b1 = y1 * inv, b2 = x2 * inv, b3 = y2 * inv;
        float cx = (b0 + b2) * 0.5f;
        float cy = (b1 + b3) * 0.5f;
        float hw = (b2 - b0) * 0.5f * 0.2f;
        float hh = (b3 - b1) * 0.5f * 0.2f;
        float px1 = fmaxf(floorf(cx - hw), 0.0f);
        float py1 = fmaxf(floorf(cy - hh), 0.0f);
        float px2 = fminf(ceilf(cx + hw), (float)fw);
        float py2 = fminf(ceilf(cy + hh), (float)fw);

        // candidate if the shrunk region overlaps this block's rows
        // (zero/invalid boxes give px2 == 0 -> px2 > px1 fails)
        bool hit = (px2 > px1) && (py2 > py1) &&
                   (py1 <= (float)by1) && (py2 > (float)by0);
        if (hit) {
            int k = atomicAdd(&s_cnt, 1);
            cbnd[k]  = make_float4(px1, py1, px2, py2);
            carea[k] = (x2 - x1) * (y2 - y1);
            cj[k]    = t;
        }
        if (fabsf(x1) + fabsf(y1) + fabsf(x2) + fabsf(y2) > 0.0f)
            atomicAdd(&s_valid, 1);
    }
    __syncthreads();

    // num_boxes written once per batch from the smallest block
    if (blockIdx.x == 85 && t == 0)
        out[OFF_NB + b] = (float)s_valid;

    const int p = p0 + t;
    if (p >= HW_TOT) return;

    const int cnt = s_cnt;
    const int   local = p - off;
    const int   y     = local >> sh;
    const int   x     = local & (fw - 1);
    const float fx    = (float)x;
    const float fy    = (float)y;

    // argmin over candidates; tie-break on smallest original index makes the
    // unordered compaction exactly reproduce argmin-first semantics.
    float bestA = 1e7f;
    int   bestJ = -1;
    for (int k = 0; k < cnt; k++) {
        float4 bb = cbnd[k];
        bool inside = (fx >= bb.x) & (fx < bb.z) & (fy >= bb.y) & (fy < bb.w);
        float a = carea[k];
        int   j = cj[k];
        if (inside && (a < bestA || (a == bestA && j < bestJ))) {
            bestA = a; bestJ = j;
        }
    }

    const int g = b * HW_TOT + p;
    float soft = 1.0f;
    float posf = 0.0f;

    if (bestJ >= 0) {
        float4 wb = sbox[bestJ];
        float sx = (fx + 0.5f) * fS;
        float sy = (fy + 0.5f) * fS;
        float l  = sx - wb.x;
        float tt = sy - wb.y;
        float r  = wb.z - sx;
        float bt = wb.w - sy;
        const float eps = 1e-6f;
        float q1 = fminf(fmaxf(fminf(l, r)  / fmaxf(fmaxf(l, r),  eps), 0.f), 1.f);
        float q2 = fminf(fmaxf(fminf(tt, bt)/ fmaxf(fmaxf(tt, bt), eps), 0.f), 1.f);
        soft = sqrtf(q1 * q2);
        posf = 1.0f;

        // one-hot class
        out[(long long)g * 82 + slbl[bestJ]] = 1.0f;

        // regression targets
        float inv4 = 0.25f * inv;                  // 1/(4*stride), exact
        float2* rp = reinterpret_cast<float2*>(out + OFF_REG + (long long)g * 6);
        rp[0] = make_float2(l * inv4, tt * inv4);
        rp[1] = make_float2(r * inv4, bt * inv4);
    }

    // every pixel: {soft, posf} tails for cls and reg
    *reinterpret_cast<float2*>(out + (long long)g * 82 + 80) = make_float2(soft, posf);
    *reinterpret_cast<float2*>(out + OFF_REG + (long long)g * 6 + 4) = make_float2(soft, posf);

    // ind (coalesced)
    out[OFF_IND + g] = (bestJ >= 0) ? (float)bestJ : -1.0f;
}

// ---------------------------------------------------------------------------
extern "C" void kernel_launch(void* const* d_in, const int* in_sizes, int n_in,
                              void* d_out, int out_size)
{
    const float* gt  = (const float*)d_in[0];
    float*       out = (float*)d_out;

    // zero-fill cls_t + reg_t regions (everything else is fully written)
    cudaMemsetAsync(d_out, 0, (size_t)OFF_IND * sizeof(float), 0);

    dim3 grid((HW_TOT + 255) / 256, B_);           // (86, 16)
    fused_kernel<<<grid, 256>>>(gt, out);
}